// round 14
// baseline (speedup 1.0000x reference)
#include <cuda_runtime.h>
#include <cstdint>

#define NB    16384
#define SN    81
#define SS    6561
#define HID   32
#define OBSW  162
#define GRID  148
#define TPB   111
#define DBLK  49                   // blocks 0..48 dense, 49..147 scatter
#define NTHREADS 512
#define STAGES 8
#define STAGE_FLOATS 6564          // 26256 B aligned window per slice
#define STAGE_BYTES  26256
#define SLOTF 416                  // staging floats per slice (405 rounded)

// out layout: [0,NB) symbolic | [NB,2NB) imm | [2NB,3NB) next | [3NB,..) nsc BxSN
//
// R13 crash root-caused: 14 consumers over 8 stages -> rotating stage
// ownership -> single-bit parity aliasing -> premature FULL-wait pass ->
// double EMPTY arrive -> mbarrier corruption. Fix: 8 consumers, warp w
// statically owns stage w and observes every phase (parity alternates).

__device__ __forceinline__ uint32_t s2u(const void* p) {
    uint32_t a;
    asm("{ .reg .u64 t; cvta.to.shared.u64 t, %1; cvt.u32.u64 %0, t; }"
        : "=r"(a) : "l"(p));
    return a;
}
__device__ __forceinline__ void mbar_init(uint32_t a, uint32_t cnt) {
    asm volatile("mbarrier.init.shared.b64 [%0], %1;" :: "r"(a), "r"(cnt) : "memory");
}
__device__ __forceinline__ void mbar_expect_tx(uint32_t a, uint32_t bytes) {
    asm volatile("mbarrier.arrive.expect_tx.shared.b64 _, [%0], %1;"
                 :: "r"(a), "r"(bytes) : "memory");
}
__device__ __forceinline__ void mbar_arrive(uint32_t a) {
    asm volatile("mbarrier.arrive.shared.b64 _, [%0];" :: "r"(a) : "memory");
}
__device__ __forceinline__ void mbar_wait(uint32_t a, uint32_t phase) {
    asm volatile(
        "{\n\t.reg .pred p;\n\t"
        "WAITLOOP_%=:\n\t"
        "mbarrier.try_wait.parity.acquire.cta.shared::cta.b64 p, [%0], %1, 0x989680;\n\t"
        "@!p bra WAITLOOP_%=;\n\t}"
        :: "r"(a), "r"(phase) : "memory");
}
__device__ __forceinline__ void tma_bulk_1d(uint32_t dst, const void* src,
                                            uint32_t bytes, uint32_t mbar) {
    asm volatile(
        "cp.async.bulk.shared::cluster.global.mbarrier::complete_tx::bytes "
        "[%0], [%1], %2, [%3];"
        :: "r"(dst), "l"(src), "r"(bytes), "r"(mbar) : "memory");
}

__device__ __forceinline__ void slice_epilogue(
    int b, int lane, const float v[3], float served,
    const float* __restrict__ W1, const float* __restrict__ W2,
    const float* __restrict__ W3, const float* __restrict__ b3,
    float* __restrict__ out)
{
    #pragma unroll
    for (int o = 16; o > 0; o >>= 1)
        served += __shfl_down_sync(0xFFFFFFFFu, served, o);
    const float imm = __shfl_sync(0xFFFFFFFFu, served, 0);

    float h1 = 0.0f;
    #pragma unroll
    for (int i = 0; i < SN; ++i) {
        const float hm = __shfl_sync(0xFFFFFFFFu, v[i >> 5], i & 31);
        h1 = fmaf(hm, __ldg(W1 + i * HID + lane), h1);
    }
    h1 = fmaxf(h1, 0.0f);

    float h2 = 0.0f;
    #pragma unroll
    for (int m = 0; m < HID; ++m)
        h2 = fmaf(__shfl_sync(0xFFFFFFFFu, h1, m), __ldg(W2 + m * HID + lane), h2);
    h2 = fmaxf(h2, 0.0f);

    float contrib = h2 * __ldg(W3 + lane);
    #pragma unroll
    for (int o = 16; o > 0; o >>= 1)
        contrib += __shfl_down_sync(0xFFFFFFFFu, contrib, o);

    if (lane == 0) {
        const float nr = contrib + __ldg(b3);
        out[b]          = imm + nr;
        out[NB + b]     = imm;
        out[2 * NB + b] = nr;
    }
}

__global__ __launch_bounds__(NTHREADS, 1) void gdvpn_kernel(
    const float* __restrict__ obs,
    const float* __restrict__ ac,
    const float* __restrict__ W1,
    const float* __restrict__ W2,
    const float* __restrict__ W3,
    const float* __restrict__ b3,
    float* __restrict__ out)
{
    extern __shared__ float sm[];
    const uint32_t smb   = s2u(sm);
    const uint32_t FULL  = smb;
    const uint32_t EMPTY = smb + 64;
    float* buf = sm + 32;              // dense ring / scatter staging (byte 128)
    const uint32_t ring_u = smb + 224; // 16B-aligned ring base
    float* ring = sm + 56;             // byte 224

    const int tid  = threadIdx.x;
    const int w    = tid >> 5;
    const int lane = tid & 31;
    const int start = blockIdx.x * TPB;
    int count = NB - start;
    if (count > TPB) count = TPB;
    if (count < 0)   count = 0;

    if (blockIdx.x < DBLK) {
        // ======== DENSE block: TMA ring, 8 consumers w/ static stage ========
        if (tid == 0) {
            #pragma unroll
            for (int s = 0; s < STAGES; ++s) {
                mbar_init(FULL + 8 * s, 1);
                mbar_init(EMPTY + 8 * s, 1);
            }
            asm volatile("fence.proxy.async.shared::cta;" ::: "memory");
        }
        __syncthreads();

        if (w == 8) {
            // producer
            if (lane == 0) {
                int stage = 0, phase = 1;  // fresh-barrier empty-wait passes at parity 1
                for (int i = 0; i < count; ++i) {
                    const size_t byte_base = (size_t)(start + i) * (SS * 4);
                    const char* src = (const char*)ac + (byte_base & ~(size_t)15);
                    mbar_wait(EMPTY + 8 * stage, phase);
                    mbar_expect_tx(FULL + 8 * stage, STAGE_BYTES);
                    tma_bulk_1d(ring_u + stage * STAGE_BYTES, src, STAGE_BYTES,
                                FULL + 8 * stage);
                    if (++stage == STAGES) { stage = 0; phase ^= 1; }
                }
            }
            return;
        }
        if (w > 8) return;

        // consumer warp w statically owns stage w: i = w, w+8, ...; parity
        // (i>>3)&1 alternates 0,1,0,... each visit -> protocol sound.
        for (int i = w; i < count; i += 8) {
            const int b     = start + i;
            const int stage = w;
            const int phase = (i >> 3) & 1;

            float dem[3];
            #pragma unroll
            for (int k = 0; k < 3; ++k) {
                const int t = lane + 32 * k;
                dem[k] = (t < SN) ? __ldg(obs + (size_t)b * OBSW + SN + t) : 0.0f;
            }

            mbar_wait(FULL + 8 * stage, phase);
            const float* sf = ring + stage * STAGE_FLOATS + (b & 3);

            float v[3];
            float served = 0.0f;
            #pragma unroll
            for (int k = 0; k < 3; ++k) {
                const int t = lane + 32 * k;
                float x = 0.0f;
                if (t < SN) {
                    const int c = t % 9;
                    const int p = 82 * t;
                    x = sf[p];
                    if (t >= 9)      x += sf[p - 729];
                    if (t < SN - 9)  x += sf[p + 729];
                    if (c > 0)       x += sf[p - 81];
                    if (c < 8)       x += sf[p + 81];
                    served += fminf(x, dem[k]);
                }
                v[k] = x;
            }
            __syncwarp();
            if (lane == 0) mbar_arrive(EMPTY + 8 * stage);

            #pragma unroll
            for (int k = 0; k < 3; ++k) {
                const int t = lane + 32 * k;
                if (t < SN) out[(size_t)3 * NB + (size_t)b * SN + t] = v[k];
            }
            slice_epilogue(b, lane, v, served, W1, W2, W3, b3, out);
        }
        return;
    }

    // ============ SCATTER block: 16 warps x 2-slice gather (no barriers) ============
    __syncthreads();
    float* ss0 = buf + w * (2 * SLOTF);
    float* ss1 = ss0 + SLOTF;

    for (int i0 = w; i0 < count; i0 += 32) {
        const int i1 = i0 + 16;
        const int b0 = start + i0;
        const int b1 = start + i1;
        const bool has1 = (i1 < count);
        const float* a0 = ac + (size_t)b0 * SS;
        const float* a1 = ac + (size_t)b1 * SS;

        #pragma unroll
        for (int it = 0; it < 13; ++it) {
            const int q = lane + it * 32;
            if (q < SN * 5) {
                const int j   = q / 5;
                const int off = q - 5 * j;
                const int c   = j % 9;
                int d; bool valid;
                switch (off) {
                    case 0: d = -9; valid = (j >= 9);     break;
                    case 1: d = -1; valid = (c > 0);      break;
                    case 2: d =  0; valid = true;         break;
                    case 3: d =  1; valid = (c < 8);      break;
                    default:d =  9; valid = (j < SN - 9); break;
                }
                const int adr = 82 * j + d;
                ss0[q] = valid ? __ldg(a0 + adr) : 0.0f;
                if (has1) ss1[q] = valid ? __ldg(a1 + adr) : 0.0f;
            }
        }
        __syncwarp();

        #pragma unroll
        for (int sl = 0; sl < 2; ++sl) {
            if (sl == 1 && !has1) break;
            const float* ss = sl ? ss1 : ss0;
            const int b = sl ? b1 : b0;

            float v[3];
            float served = 0.0f;
            #pragma unroll
            for (int k = 0; k < 3; ++k) {
                const int t = lane + 32 * k;
                float x = 0.0f;
                if (t < SN) {
                    const int c = t % 9;
                    x = ss[5 * t + 2];
                    if (t >= 9)      x += ss[5 * (t - 9) + 4];
                    if (t < SN - 9)  x += ss[5 * (t + 9) + 0];
                    if (c > 0)       x += ss[5 * (t - 1) + 3];
                    if (c < 8)       x += ss[5 * (t + 1) + 1];
                    out[(size_t)3 * NB + (size_t)b * SN + t] = x;
                    served += fminf(x, __ldg(obs + (size_t)b * OBSW + SN + t));
                }
                v[k] = x;
            }
            slice_epilogue(b, lane, v, served, W1, W2, W3, b3, out);
        }
        __syncwarp();
    }
}

extern "C" void kernel_launch(void* const* d_in, const int* in_sizes, int n_in,
                              void* d_out, int out_size)
{
    const float* obs = (const float*)d_in[0];
    const float* ac  = (const float*)d_in[1];
    const float* W1  = (const float*)d_in[2];
    const float* W2  = (const float*)d_in[3];
    const float* W3  = (const float*)d_in[4];
    const float* b3  = (const float*)d_in[5];
    float* out = (float*)d_out;

    const int smem_bytes = 224 + STAGES * STAGE_BYTES;   // 210,272 B
    cudaFuncSetAttribute(gdvpn_kernel,
                         cudaFuncAttributeMaxDynamicSharedMemorySize, smem_bytes);
    gdvpn_kernel<<<GRID, NTHREADS, smem_bytes>>>(obs, ac, W1, W2, W3, b3, out);
}

// round 15
// speedup vs baseline: 1.6787x; 1.6787x over previous
#include <cuda_runtime.h>

#define NB    16384
#define SN    81
#define HID   32
#define OBSW  162
#define BPB   8
#define NTHREADS (BPB * 32)

// out layout: [0,NB) symbolic | [NB,2NB) imm | [2NB,3NB) next | [3NB,..) nsc BxSN
//
// R3 floor kernel (61.5 us) + streaming cache hints:
//   __ldcs on the zero-reuse ac gather, __stcs on the streaming nsc output.

__global__ __launch_bounds__(NTHREADS) void gdvpn_kernel(
    const float* __restrict__ obs,   // B x 162
    const float* __restrict__ ac,    // B x 81 x 81
    const float* __restrict__ W1,    // 81 x 32
    const float* __restrict__ W2,    // 32 x 32
    const float* __restrict__ W3,    // 32
    const float* __restrict__ b3,    // 1
    float* __restrict__ out)
{
    // sh[w][5*j+off] = ac[b, j, j+D[off]] (0 if invalid), D = {-9,-1,0,+1,+9}.
    // Stride 5 coprime with 32 -> conflict-free LDS.
    __shared__ float sh[BPB][SN * 5];
    __shared__ float sh_nsc[BPB][SN];

    const int w    = threadIdx.x >> 5;   // warp id = slice within block
    const int lane = threadIdx.x & 31;
    const int b    = blockIdx.x * BPB + w;
    const float* acb = ac + (size_t)b * (SN * SN);

    // ---- Phase 1: gather (13 independent predicated loads per lane) ----
    #pragma unroll
    for (int it = 0; it < 13; ++it) {
        const int q = lane + it * 32;
        if (q < SN * 5) {
            const int j   = q / 5;
            const int off = q - 5 * j;
            const int c   = j % 9;
            int d; bool valid;
            switch (off) {
                case 0: d = -9; valid = (j >= 9);     break;
                case 1: d = -1; valid = (c > 0);      break;
                case 2: d =  0; valid = true;         break;
                case 3: d =  1; valid = (c < 8);      break;
                default:d =  9; valid = (j < SN - 9); break;
            }
            sh[w][q] = valid ? __ldcs(acb + 82 * j + d) : 0.0f;
        }
    }
    __syncwarp();

    // ---- Phase 2: nsc + served (lane owns t = lane, lane+32, lane+64) ----
    float served = 0.0f;
    #pragma unroll
    for (int k = 0; k < 3; ++k) {
        const int t = lane + k * 32;
        if (t < SN) {
            const int c = t % 9;
            float v = sh[w][5 * t + 2];                       // j = t
            if (t >= 9)      v += sh[w][5 * (t - 9) + 4];     // j = t-9
            if (t < SN - 9)  v += sh[w][5 * (t + 9) + 0];     // j = t+9
            if (c > 0)       v += sh[w][5 * (t - 1) + 3];     // j = t-1
            if (c < 8)       v += sh[w][5 * (t + 1) + 1];     // j = t+1

            sh_nsc[w][t] = v;
            __stcs(out + (size_t)3 * NB + (size_t)b * SN + t, v);

            const float demand = __ldg(obs + (size_t)b * OBSW + SN + t);
            served += fminf(v, demand);
        }
    }

    // warp-reduce served -> immediate reward
    #pragma unroll
    for (int o = 16; o > 0; o >>= 1)
        served += __shfl_down_sync(0xFFFFFFFFu, served, o);
    const float imm = __shfl_sync(0xFFFFFFFFu, served, 0);
    __syncwarp();

    // ---- Phase 3: MLP (W1/W2 L1-resident) ----
    float h1 = 0.0f;
    #pragma unroll
    for (int i = 0; i < SN; ++i)
        h1 = fmaf(sh_nsc[w][i], __ldg(W1 + i * HID + lane), h1);
    h1 = fmaxf(h1, 0.0f);

    float h2 = 0.0f;
    #pragma unroll
    for (int m = 0; m < HID; ++m)
        h2 = fmaf(__shfl_sync(0xFFFFFFFFu, h1, m), __ldg(W2 + m * HID + lane), h2);
    h2 = fmaxf(h2, 0.0f);

    float contrib = h2 * __ldg(W3 + lane);
    #pragma unroll
    for (int o = 16; o > 0; o >>= 1)
        contrib += __shfl_down_sync(0xFFFFFFFFu, contrib, o);

    if (lane == 0) {
        const float nr = contrib + __ldg(b3);
        out[b]          = imm + nr;
        out[NB + b]     = imm;
        out[2 * NB + b] = nr;
    }
}

extern "C" void kernel_launch(void* const* d_in, const int* in_sizes, int n_in,
                              void* d_out, int out_size)
{
    const float* obs = (const float*)d_in[0];
    const float* ac  = (const float*)d_in[1];
    const float* W1  = (const float*)d_in[2];
    const float* W2  = (const float*)d_in[3];
    const float* W3  = (const float*)d_in[4];
    const float* b3  = (const float*)d_in[5];
    float* out = (float*)d_out;

    gdvpn_kernel<<<NB / BPB, NTHREADS>>>(obs, ac, W1, W2, W3, b3, out);
}

// round 16
// speedup vs baseline: 1.7178x; 1.0232x over previous
#include <cuda_runtime.h>

#define NB    16384
#define SN    81
#define HID   32
#define OBSW  162
#define BPB   8
#define NTHREADS (BPB * 32)

// out layout: [0,NB) symbolic | [NB,2NB) imm | [2NB,3NB) next | [3NB,..) nsc BxSN
//
// Floor kernel (R15, 59.2 us) + final trims: obs demand prefetched above the
// gather (overlaps latency), __ldcs on obs, __stcs on all outputs.

__global__ __launch_bounds__(NTHREADS) void gdvpn_kernel(
    const float* __restrict__ obs,   // B x 162
    const float* __restrict__ ac,    // B x 81 x 81
    const float* __restrict__ W1,    // 81 x 32
    const float* __restrict__ W2,    // 32 x 32
    const float* __restrict__ W3,    // 32
    const float* __restrict__ b3,    // 1
    float* __restrict__ out)
{
    // sh[w][5*j+off] = ac[b, j, j+D[off]] (0 if invalid), D = {-9,-1,0,+1,+9}.
    // Stride 5 coprime with 32 -> conflict-free LDS.
    __shared__ float sh[BPB][SN * 5];
    __shared__ float sh_nsc[BPB][SN];

    const int w    = threadIdx.x >> 5;   // warp id = slice within block
    const int lane = threadIdx.x & 31;
    const int b    = blockIdx.x * BPB + w;
    const float* acb = ac + (size_t)b * (SN * SN);

    // ---- Phase 0: prefetch demand (overlaps entirely under the gather) ----
    float dem[3];
    #pragma unroll
    for (int k = 0; k < 3; ++k) {
        const int t = lane + 32 * k;
        dem[k] = (t < SN) ? __ldcs(obs + (size_t)b * OBSW + SN + t) : 0.0f;
    }

    // ---- Phase 1: gather (13 independent predicated loads per lane) ----
    #pragma unroll
    for (int it = 0; it < 13; ++it) {
        const int q = lane + it * 32;
        if (q < SN * 5) {
            const int j   = q / 5;
            const int off = q - 5 * j;
            const int c   = j % 9;
            int d; bool valid;
            switch (off) {
                case 0: d = -9; valid = (j >= 9);     break;
                case 1: d = -1; valid = (c > 0);      break;
                case 2: d =  0; valid = true;         break;
                case 3: d =  1; valid = (c < 8);      break;
                default:d =  9; valid = (j < SN - 9); break;
            }
            sh[w][q] = valid ? __ldcs(acb + 82 * j + d) : 0.0f;
        }
    }
    __syncwarp();

    // ---- Phase 2: nsc + served (lane owns t = lane, lane+32, lane+64) ----
    float served = 0.0f;
    #pragma unroll
    for (int k = 0; k < 3; ++k) {
        const int t = lane + k * 32;
        if (t < SN) {
            const int c = t % 9;
            float v = sh[w][5 * t + 2];                       // j = t
            if (t >= 9)      v += sh[w][5 * (t - 9) + 4];     // j = t-9
            if (t < SN - 9)  v += sh[w][5 * (t + 9) + 0];     // j = t+9
            if (c > 0)       v += sh[w][5 * (t - 1) + 3];     // j = t-1
            if (c < 8)       v += sh[w][5 * (t + 1) + 1];     // j = t+1

            sh_nsc[w][t] = v;
            __stcs(out + (size_t)3 * NB + (size_t)b * SN + t, v);

            served += fminf(v, dem[k]);
        }
    }

    // warp-reduce served -> immediate reward
    #pragma unroll
    for (int o = 16; o > 0; o >>= 1)
        served += __shfl_down_sync(0xFFFFFFFFu, served, o);
    const float imm = __shfl_sync(0xFFFFFFFFu, served, 0);
    __syncwarp();

    // ---- Phase 3: MLP (W1/W2 L1-resident) ----
    float h1 = 0.0f;
    #pragma unroll
    for (int i = 0; i < SN; ++i)
        h1 = fmaf(sh_nsc[w][i], __ldg(W1 + i * HID + lane), h1);
    h1 = fmaxf(h1, 0.0f);

    float h2 = 0.0f;
    #pragma unroll
    for (int m = 0; m < HID; ++m)
        h2 = fmaf(__shfl_sync(0xFFFFFFFFu, h1, m), __ldg(W2 + m * HID + lane), h2);
    h2 = fmaxf(h2, 0.0f);

    float contrib = h2 * __ldg(W3 + lane);
    #pragma unroll
    for (int o = 16; o > 0; o >>= 1)
        contrib += __shfl_down_sync(0xFFFFFFFFu, contrib, o);

    if (lane == 0) {
        const float nr = contrib + __ldg(b3);
        __stcs(out + b,          imm + nr);
        __stcs(out + NB + b,     imm);
        __stcs(out + 2 * NB + b, nr);
    }
}

extern "C" void kernel_launch(void* const* d_in, const int* in_sizes, int n_in,
                              void* d_out, int out_size)
{
    const float* obs = (const float*)d_in[0];
    const float* ac  = (const float*)d_in[1];
    const float* W1  = (const float*)d_in[2];
    const float* W2  = (const float*)d_in[3];
    const float* W3  = (const float*)d_in[4];
    const float* b3  = (const float*)d_in[5];
    float* out = (float*)d_out;

    gdvpn_kernel<<<NB / BPB, NTHREADS>>>(obs, ac, W1, W2, W3, b3, out);
}